// round 1
// baseline (speedup 1.0000x reference)
#include <cuda_runtime.h>
#include <cuda_bf16.h>

#define NN   2048
#define EE   65536
#define FIN  128
#define HH   16
#define N2   (NN * NN)

// ---------------- scratch (no allocations allowed) ----------------
__device__ float g_deg[NN];
__device__ float g_dinv[NN];
__device__ float g_xw1[NN * HH];
__device__ float g_acc1[NN * HH];
__device__ float g_hw2[NN * 2];
__device__ float g_acc2[NN * 2];
__device__ float g_A[NN * HH];   // h @ Wc1[0:16] + bc1
__device__ float g_B[NN * HH];   // h @ Wc1[16:32]
__device__ int   g_is32;         // 1 if edge_index is int32, 0 if int64

// edge_index accessor: layout detected at runtime
__device__ __forceinline__ int ld_idx(const void* ei, int pos) {
    if (g_is32) return ((const int*)ei)[pos];
    return (int)(((const long long*)ei)[pos]);
}

// ---------------- init: zero accumulators, deg=1 (self loop), flag=0 ----
__global__ void k_init() {
    int i = blockIdx.x * blockDim.x + threadIdx.x;
    if (i < NN * HH) g_acc1[i] = 0.f;
    if (i < NN * 2)  g_acc2[i] = 0.f;
    if (i < NN)      g_deg[i]  = 1.f;
    if (i == 0)      g_is32    = 0;
}

// ---------------- detect int32 vs int64 edge_index ----------------
// Read the first EE entries as u64. For a true int64 buffer these are the
// src indices (all < 2048). For an int32 buffer each u64 packs two node ids,
// so the value is >= 2^32 whenever the high half is nonzero (prob ~1 per pair)
// -> guaranteed detection over 65536 samples. Reads stay within the smaller
// (int32) buffer size.
__global__ void k_detect(const void* ei) {
    int e = blockIdx.x * blockDim.x + threadIdx.x;
    if (e >= EE) return;
    unsigned long long v = ((const unsigned long long*)ei)[e];
    if (v >= 2048ULL) atomicOr(&g_is32, 1);
}

// ---------------- degree (includes self loop via init=1) ----------------
__global__ void k_deg(const void* ei) {
    int e = blockIdx.x * blockDim.x + threadIdx.x;
    if (e >= EE) return;
    int d = ld_idx(ei, EE + e);
    atomicAdd(&g_deg[d], 1.f);
}

__global__ void k_dinv() {
    int i = blockIdx.x * blockDim.x + threadIdx.x;
    if (i < NN) g_dinv[i] = rsqrtf(g_deg[i]);
}

// ---------------- xw1 = x @ W1  (2048x128 @ 128x16) ----------------
__global__ void k_xw1(const float* __restrict__ x, const float* __restrict__ W1) {
    int id = blockIdx.x * blockDim.x + threadIdx.x;   // 32768 threads
    if (id >= NN * HH) return;
    int i = id >> 4, f = id & 15;
    const float* xr = x + i * FIN;
    float s = 0.f;
    #pragma unroll 8
    for (int k = 0; k < FIN; k++) s = fmaf(xr[k], W1[k * HH + f], s);
    g_xw1[id] = s;
}

// ---------------- scatter layer 1 ----------------
__global__ void k_scatter1(const void* ei) {
    int e = blockIdx.x * blockDim.x + threadIdx.x;
    if (e >= EE) return;
    int s = ld_idx(ei, e);
    int d = ld_idx(ei, EE + e);
    float nrm = g_dinv[s] * g_dinv[d];
    const float* xs = &g_xw1[s * HH];
    float* ad = &g_acc1[d * HH];
    #pragma unroll
    for (int f = 0; f < HH; f++) atomicAdd(&ad[f], nrm * xs[f]);
}

// ---------------- h = relu(gcn1), then hw2 = h@W2, A = h@Wc1_top + bc1,
//                  B = h@Wc1_bot, fused per node ----------------
__global__ void k_hAB(const float* __restrict__ b1, const float* __restrict__ W2,
                      const float* __restrict__ Wc1, const float* __restrict__ bc1) {
    int i = blockIdx.x * blockDim.x + threadIdx.x;
    if (i >= NN) return;
    float di = g_dinv[i];
    float d2 = di * di;
    float h[HH];
    #pragma unroll
    for (int f = 0; f < HH; f++) {
        float v = g_acc1[i * HH + f] + d2 * g_xw1[i * HH + f] + b1[f];
        h[f] = fmaxf(v, 0.f);
    }
    float c0 = 0.f, c1 = 0.f;
    #pragma unroll
    for (int f = 0; f < HH; f++) {
        c0 = fmaf(h[f], W2[f * 2 + 0], c0);
        c1 = fmaf(h[f], W2[f * 2 + 1], c1);
    }
    g_hw2[i * 2 + 0] = c0;
    g_hw2[i * 2 + 1] = c1;
    #pragma unroll
    for (int o = 0; o < HH; o++) {
        float a = bc1[o], b = 0.f;
        #pragma unroll
        for (int f = 0; f < HH; f++) {
            a = fmaf(h[f], Wc1[f * HH + o], a);
            b = fmaf(h[f], Wc1[(HH + f) * HH + o], b);
        }
        g_A[i * HH + o] = a;
        g_B[i * HH + o] = b;
    }
}

// ---------------- scatter layer 2 ----------------
__global__ void k_scatter2(const void* ei) {
    int e = blockIdx.x * blockDim.x + threadIdx.x;
    if (e >= EE) return;
    int s = ld_idx(ei, e);
    int d = ld_idx(ei, EE + e);
    float nrm = g_dinv[s] * g_dinv[d];
    atomicAdd(&g_acc2[d * 2 + 0], nrm * g_hw2[s * 2 + 0]);
    atomicAdd(&g_acc2[d * 2 + 1], nrm * g_hw2[s * 2 + 1]);
}

// ---------------- node_out ----------------
__global__ void k_nodeout(const float* __restrict__ b2, float* __restrict__ out) {
    int i = blockIdx.x * blockDim.x + threadIdx.x;
    if (i >= NN) return;
    float di = g_dinv[i];
    float d2 = di * di;
    out[i * 2 + 0] = g_acc2[i * 2 + 0] + d2 * g_hw2[i * 2 + 0] + b2[0];
    out[i * 2 + 1] = g_acc2[i * 2 + 1] + d2 * g_hw2[i * 2 + 1] + b2[1];
}

// ---------------- the big pair kernel: 2048 x 2048 pairs ----------------
// e(i,j) = sigmoid( sum_f relu(A[i][f] + B[j][f]) * Wc2[f] + bc2 )
// Also writes full_edge_index rows (start=i, end=j) as float.
__global__ void __launch_bounds__(256, 4) k_pair(const float* __restrict__ Wc2,
                                                 const float* __restrict__ bc2p,
                                                 float* __restrict__ out) {
    int i = blockIdx.x;
    float a[HH], w[HH];
    const float4* ap = (const float4*)&g_A[i * HH];
    float4 a0 = ap[0], a1 = ap[1], a2 = ap[2], a3 = ap[3];
    a[0]=a0.x; a[1]=a0.y; a[2]=a0.z; a[3]=a0.w;
    a[4]=a1.x; a[5]=a1.y; a[6]=a1.z; a[7]=a1.w;
    a[8]=a2.x; a[9]=a2.y; a[10]=a2.z; a[11]=a2.w;
    a[12]=a3.x; a[13]=a3.y; a[14]=a3.z; a[15]=a3.w;
    #pragma unroll
    for (int f = 0; f < HH; f++) w[f] = Wc2[f];
    float bb = bc2p[0];

    float* eo = out + NN * 2 + (long long)i * NN;
    float* s0 = out + NN * 2 + (long long)N2 + (long long)i * NN;
    float* s1 = out + NN * 2 + 2LL * N2 + (long long)i * NN;
    float fi = (float)i;

    #pragma unroll
    for (int it = 0; it < NN / 256; it++) {
        int j = it * 256 + threadIdx.x;
        const float4* bp = (const float4*)&g_B[j * HH];
        float4 b0 = bp[0], b1 = bp[1], b2 = bp[2], b3 = bp[3];
        float s = bb;
        s = fmaf(fmaxf(a[0]  + b0.x, 0.f), w[0],  s);
        s = fmaf(fmaxf(a[1]  + b0.y, 0.f), w[1],  s);
        s = fmaf(fmaxf(a[2]  + b0.z, 0.f), w[2],  s);
        s = fmaf(fmaxf(a[3]  + b0.w, 0.f), w[3],  s);
        s = fmaf(fmaxf(a[4]  + b1.x, 0.f), w[4],  s);
        s = fmaf(fmaxf(a[5]  + b1.y, 0.f), w[5],  s);
        s = fmaf(fmaxf(a[6]  + b1.z, 0.f), w[6],  s);
        s = fmaf(fmaxf(a[7]  + b1.w, 0.f), w[7],  s);
        s = fmaf(fmaxf(a[8]  + b2.x, 0.f), w[8],  s);
        s = fmaf(fmaxf(a[9]  + b2.y, 0.f), w[9],  s);
        s = fmaf(fmaxf(a[10] + b2.z, 0.f), w[10], s);
        s = fmaf(fmaxf(a[11] + b2.w, 0.f), w[11], s);
        s = fmaf(fmaxf(a[12] + b3.x, 0.f), w[12], s);
        s = fmaf(fmaxf(a[13] + b3.y, 0.f), w[13], s);
        s = fmaf(fmaxf(a[14] + b3.z, 0.f), w[14], s);
        s = fmaf(fmaxf(a[15] + b3.w, 0.f), w[15], s);
        float sig = 1.f / (1.f + __expf(-s));
        eo[j] = sig;
        s0[j] = fi;
        s1[j] = (float)j;
    }
}

// ---------------- launch ----------------
extern "C" void kernel_launch(void* const* d_in, const int* in_sizes, int n_in,
                              void* d_out, int out_size) {
    const float* x   = (const float*)d_in[0];
    const void*  ei  = d_in[1];                 // int32 or int64, detected on device
    const float* W1  = (const float*)d_in[2];
    const float* b1  = (const float*)d_in[3];
    const float* W2  = (const float*)d_in[4];
    const float* b2  = (const float*)d_in[5];
    const float* Wc1 = (const float*)d_in[6];
    const float* bc1 = (const float*)d_in[7];
    const float* Wc2 = (const float*)d_in[8];
    const float* bc2 = (const float*)d_in[9];
    float* out = (float*)d_out;

    k_init<<<(NN * HH + 255) / 256, 256>>>();
    k_detect<<<EE / 256, 256>>>(ei);
    k_deg<<<EE / 256, 256>>>(ei);
    k_dinv<<<NN / 256, 256>>>();
    k_xw1<<<(NN * HH + 255) / 256, 256>>>(x, W1);
    k_scatter1<<<EE / 256, 256>>>(ei);
    k_hAB<<<NN / 256, 256>>>(b1, W2, Wc1, bc1);
    k_scatter2<<<EE / 256, 256>>>(ei);
    k_nodeout<<<NN / 256, 256>>>(b2, out);
    k_pair<<<NN, 256>>>(Wc2, bc2, out);
}